// round 2
// baseline (speedup 1.0000x reference)
#include <cuda_runtime.h>

#define N_NODES   50000
#define N_EDGES   550000
#define HID       128
#define OUT_CH    64
#define N_GRAPHS  64
#define NEG_SLOPE 0.2f

typedef unsigned long long ull;

// ---------------- device scratch ----------------
__device__ float g_h [N_NODES * HID];
__device__ float g_hw[N_NODES * HID];
__device__ float g_ssrc[N_NODES];
__device__ float g_sdst[N_NODES];
__device__ int   g_cnt [N_NODES];
__device__ int   g_off [N_NODES + 1];
__device__ int   g_pos [N_NODES];       // atomic fill cursors (copy of offsets)
__device__ int   g_csrc[N_EDGES];
__device__ int   g_gstart[N_GRAPHS + 1];
__device__ float g_pool[N_GRAPHS * HID];

// ---------------- f32x2 helpers ----------------
__device__ __forceinline__ void ffma2(ull& d, ull a, ull b) {
    asm("fma.rn.f32x2 %0, %1, %2, %0;" : "+l"(d) : "l"(a), "l"(b));
}
__device__ __forceinline__ ull pack_dup(float x) {
    ull r; unsigned xi = __float_as_uint(x);
    asm("mov.b64 %0, {%1, %1};" : "=l"(r) : "r"(xi));
    return r;
}
__device__ __forceinline__ ull pack2(float x, float y) {
    ull r; unsigned xi = __float_as_uint(x), yi = __float_as_uint(y);
    asm("mov.b64 %0, {%1, %2};" : "=l"(r) : "r"(xi), "r"(yi));
    return r;
}
__device__ __forceinline__ float2 unpack2(ull v) {
    unsigned x, y;
    asm("mov.b64 {%0, %1}, %2;" : "=r"(x), "=r"(y) : "l"(v));
    return make_float2(__uint_as_float(x), __uint_as_float(y));
}

// ---------------- CSR build ----------------
__global__ void k_zero() {
    int i = blockIdx.x * blockDim.x + threadIdx.x;
    if (i < N_NODES) g_cnt[i] = 0;
}

__global__ void k_hist(const int* __restrict__ dst) {
    for (int i = blockIdx.x * blockDim.x + threadIdx.x; i < N_EDGES;
         i += gridDim.x * blockDim.x)
        atomicAdd(&g_cnt[dst[i]], 1);
}

__global__ void k_scan() {
    __shared__ int part[1024];
    const int t  = threadIdx.x;
    const int CH = (N_NODES + 1023) / 1024;
    int base = t * CH;
    int s = 0;
    for (int i = 0; i < CH; i++) {
        int idx = base + i;
        if (idx < N_NODES) s += g_cnt[idx];
    }
    part[t] = s;
    __syncthreads();
    for (int d = 1; d < 1024; d <<= 1) {
        int v = (t >= d) ? part[t - d] : 0;
        __syncthreads();
        part[t] += v;
        __syncthreads();
    }
    int run = (t == 0) ? 0 : part[t - 1];
    for (int i = 0; i < CH; i++) {
        int idx = base + i;
        if (idx < N_NODES) { g_off[idx] = run; g_pos[idx] = run; run += g_cnt[idx]; }
    }
    if (t == 1023) g_off[N_NODES] = part[1023];
}

__global__ void k_fillcsr(const int* __restrict__ src, const int* __restrict__ dst) {
    for (int i = blockIdx.x * blockDim.x + threadIdx.x; i < N_EDGES;
         i += gridDim.x * blockDim.x) {
        int pos = atomicAdd(&g_pos[dst[i]], 1);
        g_csrc[pos] = src[i];
    }
}

// ---------------- embedding gather ----------------
__global__ void k_embed(const int* __restrict__ x, const float* __restrict__ emb) {
    int i = blockIdx.x * blockDim.x + threadIdx.x;
    if (i >= N_NODES * 32) return;
    int node = i >> 5, lane = i & 31;
    ((float4*)g_h)[i] = ((const float4*)emb)[x[node] * 32 + lane];
}

// ---------------- GEMM (f32x2) with fused attention scores ----------------
// block 256 threads -> 64 rows x 128 cols tile; thread = 4 rows x 8 cols (4 f32x2 col pairs)
#define GEMM_SMEM ((64 * 132 + 128 * 128) * 4)
__global__ void k_gemm(const float* __restrict__ W,
                       const float* __restrict__ asrc,
                       const float* __restrict__ adst) {
    extern __shared__ float sm[];
    float*  As  = sm;                       // 64 x 132
    float4* Ws4 = (float4*)(sm + 64 * 132); // 128 x 32 float4

    const int tid = threadIdx.x;
    const int ct  = tid & 15;
    const int rt  = tid >> 4;
    const int rowbase = blockIdx.x * 64;

    const float4* Wg4 = (const float4*)W;
#pragma unroll
    for (int j = 0; j < 16; j++) Ws4[tid + j * 256] = Wg4[tid + j * 256];

    const float4* Ag4 = (const float4*)g_h;
#pragma unroll
    for (int j = 0; j < 8; j++) {
        int idx = tid + j * 256;
        int r = idx >> 5, c4 = idx & 31;
        int grow = rowbase + r;
        float4 v = (grow < N_NODES) ? Ag4[grow * 32 + c4]
                                    : make_float4(0.f, 0.f, 0.f, 0.f);
        *(float4*)&As[r * 132 + c4 * 4] = v;
    }
    __syncthreads();

    ull acc[4][4];
#pragma unroll
    for (int i = 0; i < 4; i++)
#pragma unroll
        for (int p = 0; p < 4; p++) acc[i][p] = 0ULL;

    const int r0 = rt * 4;
#pragma unroll 4
    for (int k = 0; k < 128; k++) {
        ull aa0 = pack_dup(As[(r0 + 0) * 132 + k]);
        ull aa1 = pack_dup(As[(r0 + 1) * 132 + k]);
        ull aa2 = pack_dup(As[(r0 + 2) * 132 + k]);
        ull aa3 = pack_dup(As[(r0 + 3) * 132 + k]);
        float4 b0 = Ws4[k * 32 + ct];
        float4 b1 = Ws4[k * 32 + 16 + ct];
        ull p0 = pack2(b0.x, b0.y);
        ull p1 = pack2(b0.z, b0.w);
        ull p2 = pack2(b1.x, b1.y);
        ull p3 = pack2(b1.z, b1.w);
        ffma2(acc[0][0], aa0, p0); ffma2(acc[0][1], aa0, p1);
        ffma2(acc[0][2], aa0, p2); ffma2(acc[0][3], aa0, p3);
        ffma2(acc[1][0], aa1, p0); ffma2(acc[1][1], aa1, p1);
        ffma2(acc[1][2], aa1, p2); ffma2(acc[1][3], aa1, p3);
        ffma2(acc[2][0], aa2, p0); ffma2(acc[2][1], aa2, p1);
        ffma2(acc[2][2], aa2, p2); ffma2(acc[2][3], aa2, p3);
        ffma2(acc[3][0], aa3, p0); ffma2(acc[3][1], aa3, p1);
        ffma2(acc[3][2], aa3, p2); ffma2(acc[3][3], aa3, p3);
    }

    // epilogue: write C + fused score partials
    const int c0 = ct * 4;        // cols c0..c0+3 and 64+c0..64+c0+3
    float as[8], ad[8];
#pragma unroll
    for (int t = 0; t < 4; t++) {
        as[t]     = asrc[c0 + t];      as[4 + t] = asrc[64 + c0 + t];
        ad[t]     = adst[c0 + t];      ad[4 + t] = adst[64 + c0 + t];
    }

    float4* C4 = (float4*)g_hw;
    float sA[4], sB[4];
#pragma unroll
    for (int i = 0; i < 4; i++) {
        float2 f0 = unpack2(acc[i][0]);
        float2 f1 = unpack2(acc[i][1]);
        float2 f2 = unpack2(acc[i][2]);
        float2 f3 = unpack2(acc[i][3]);
        int row = rowbase + r0 + i;
        if (row < N_NODES) {
            C4[row * 32 + ct]      = make_float4(f0.x, f0.y, f1.x, f1.y);
            C4[row * 32 + 16 + ct] = make_float4(f2.x, f2.y, f3.x, f3.y);
        }
        sA[i] = f0.x * as[0] + f0.y * as[1] + f1.x * as[2] + f1.y * as[3]
              + f2.x * as[4] + f2.y * as[5] + f3.x * as[6] + f3.y * as[7];
        sB[i] = f0.x * ad[0] + f0.y * ad[1] + f1.x * ad[2] + f1.y * ad[3]
              + f2.x * ad[4] + f2.y * ad[5] + f3.x * ad[6] + f3.y * ad[7];
    }
#pragma unroll
    for (int off = 1; off < 16; off <<= 1) {
#pragma unroll
        for (int i = 0; i < 4; i++) {
            sA[i] += __shfl_xor_sync(0xffffffffu, sA[i], off);
            sB[i] += __shfl_xor_sync(0xffffffffu, sB[i], off);
        }
    }
    if (ct == 0) {
#pragma unroll
        for (int i = 0; i < 4; i++) {
            int row = rowbase + r0 + i;
            if (row < N_NODES) { g_ssrc[row] = sA[i]; g_sdst[row] = sB[i]; }
        }
    }
}

// ---------------- per-node online-softmax aggregation (warp per dst) ----------------
__global__ void k_agg(const float* __restrict__ bias, int relu) {
    int node = (blockIdx.x * blockDim.x + threadIdx.x) >> 5;
    int lane = threadIdx.x & 31;
    if (node >= N_NODES) return;

    const int beg = g_off[node];
    const int end = g_off[node + 1];
    const float sd = g_sdst[node];
    const float4* hw4 = (const float4*)g_hw;

    float m = -1e30f, den = 0.f;
    float4 acc = make_float4(0.f, 0.f, 0.f, 0.f);

    for (int e = beg; e < end; e++) {
        int src = g_csrc[e];
        float t = g_ssrc[src] + sd;
        t = (t > 0.f) ? t : NEG_SLOPE * t;
        float4 v = hw4[src * 32 + lane];
        if (t > m) {                        // warp-uniform branch
            float f = __expf(m - t);
            den = den * f + 1.f;
            acc.x = acc.x * f + v.x; acc.y = acc.y * f + v.y;
            acc.z = acc.z * f + v.z; acc.w = acc.w * f + v.w;
            m = t;
        } else {
            float w = __expf(t - m);
            den += w;
            acc.x += w * v.x; acc.y += w * v.y;
            acc.z += w * v.z; acc.w += w * v.w;
        }
    }
    float inv = 1.f / den;
    float4 b = ((const float4*)bias)[lane];
    float4 o;
    o.x = acc.x * inv + b.x; o.y = acc.y * inv + b.y;
    o.z = acc.z * inv + b.z; o.w = acc.w * inv + b.w;
    if (relu) {
        o.x = fmaxf(o.x, 0.f); o.y = fmaxf(o.y, 0.f);
        o.z = fmaxf(o.z, 0.f); o.w = fmaxf(o.w, 0.f);
    }
    ((float4*)g_h)[node * 32 + lane] = o;
}

// ---------------- pooling + projection ----------------
__global__ void k_gbounds(const int* __restrict__ batch) {
    int g = threadIdx.x;
    if (g > N_GRAPHS) return;
    int lo = 0, hi = N_NODES;
    while (lo < hi) {
        int mid = (lo + hi) >> 1;
        if (batch[mid] < g) lo = mid + 1; else hi = mid;
    }
    g_gstart[g] = lo;
}

__global__ void k_pool() {
    int g = blockIdx.x;
    int c = threadIdx.x;
    int s = g_gstart[g], e = g_gstart[g + 1];
    float a0 = 0.f, a1 = 0.f, a2 = 0.f, a3 = 0.f;
    int i = s;
    for (; i + 3 < e; i += 4) {
        a0 += g_h[(i + 0) * HID + c];
        a1 += g_h[(i + 1) * HID + c];
        a2 += g_h[(i + 2) * HID + c];
        a3 += g_h[(i + 3) * HID + c];
    }
    for (; i < e; i++) a0 += g_h[i * HID + c];
    float cnt = (float)(e - s);
    g_pool[g * HID + c] = (a0 + a1 + a2 + a3) / fmaxf(cnt, 1.f);
}

__global__ void k_final(const float* __restrict__ Wout, const float* __restrict__ bout,
                        float* __restrict__ out) {
    int g = blockIdx.x;
    int o = threadIdx.x;
    float acc = 0.f;
#pragma unroll 4
    for (int c = 0; c < HID; c++)
        acc += g_pool[g * HID + c] * Wout[c * OUT_CH + o];
    out[g * OUT_CH + o] = acc + bout[o];
}

// ---------------- launch ----------------
extern "C" void kernel_launch(void* const* d_in, const int* in_sizes, int n_in,
                              void* d_out, int out_size) {
    const int*   x     = (const int*)  d_in[0];
    const int*   ei    = (const int*)  d_in[1];
    const int*   batch = (const int*)  d_in[2];
    const float* emb   = (const float*)d_in[3];
    const float* Ws    = (const float*)d_in[4];
    const float* asrc  = (const float*)d_in[5];
    const float* adst  = (const float*)d_in[6];
    const float* bs    = (const float*)d_in[7];
    const float* Wout  = (const float*)d_in[8];
    const float* bout  = (const float*)d_in[9];
    float* out = (float*)d_out;

    const int* src = ei;
    const int* dst = ei + N_EDGES;

    cudaFuncSetAttribute(k_gemm, cudaFuncAttributeMaxDynamicSharedMemorySize, GEMM_SMEM);

    k_zero<<<(N_NODES + 255) / 256, 256>>>();
    k_hist<<<1024, 256>>>(dst);
    k_scan<<<1, 1024>>>();
    k_fillcsr<<<1024, 256>>>(src, dst);

    k_embed<<<(N_NODES * 32 + 255) / 256, 256>>>(x, emb);

    const int gemm_blocks = (N_NODES + 63) / 64;
    const int warp_blocks = (N_NODES * 32 + 255) / 256;
    for (int l = 0; l < 3; l++) {
        k_gemm<<<gemm_blocks, 256, GEMM_SMEM>>>(Ws + l * HID * HID,
                                                asrc + l * HID, adst + l * HID);
        k_agg<<<warp_blocks, 256>>>(bs + l * HID, (l < 2) ? 1 : 0);
    }

    k_gbounds<<<1, 128>>>(batch);
    k_pool<<<N_GRAPHS, HID>>>();
    k_final<<<N_GRAPHS, OUT_CH>>>(Wout, bout, out);
}

// round 4
// speedup vs baseline: 1.2288x; 1.2288x over previous
#include <cuda_runtime.h>
#include <cuda_bf16.h>
#include <cstdint>

#define N_NODES   50000
#define N_EDGES   550000
#define HID       128
#define OUT_CH    64
#define N_GRAPHS  64
#define NEG_SLOPE 0.2f

// ---------------- device scratch ----------------
__device__ float g_h [N_NODES * HID];
__device__ float g_hw[N_NODES * HID];
__device__ float g_ssrc[N_NODES];
__device__ float g_sdst[N_NODES];
__device__ int   g_cnt [N_NODES];
__device__ int   g_off [N_NODES + 1];
__device__ int   g_pos [N_NODES];
__device__ int   g_csrc[N_EDGES];
__device__ int   g_gstart[N_GRAPHS + 1];
__device__ float g_pool[N_GRAPHS * HID];
// W transposed + bf16 hi/lo split: [3][128 n][128 k]
__device__ __nv_bfloat16 g_wbh[3 * 128 * 128];
__device__ __nv_bfloat16 g_wbl[3 * 128 * 128];

// ---------------- helpers ----------------
__device__ __forceinline__ uint32_t smem_u32(const void* p) {
    uint32_t a;
    asm("{ .reg .u64 t; cvta.to.shared.u64 t, %1; cvt.u32.u64 %0, t; }"
        : "=r"(a) : "l"(p));
    return a;
}
__device__ __forceinline__ void ldsm_x4(uint32_t& r0, uint32_t& r1,
                                        uint32_t& r2, uint32_t& r3, uint32_t addr) {
    asm volatile("ldmatrix.sync.aligned.m8n8.x4.shared.b16 {%0,%1,%2,%3}, [%4];"
                 : "=r"(r0), "=r"(r1), "=r"(r2), "=r"(r3) : "r"(addr));
}
__device__ __forceinline__ void mma_bf16(float* c, const uint32_t* a,
                                         uint32_t b0, uint32_t b1) {
    asm volatile(
        "mma.sync.aligned.m16n8k16.row.col.f32.bf16.bf16.f32 "
        "{%0,%1,%2,%3}, {%4,%5,%6,%7}, {%8,%9}, {%0,%1,%2,%3};"
        : "+f"(c[0]), "+f"(c[1]), "+f"(c[2]), "+f"(c[3])
        : "r"(a[0]), "r"(a[1]), "r"(a[2]), "r"(a[3]), "r"(b0), "r"(b1));
}
__device__ __forceinline__ uint32_t bf2_bits(__nv_bfloat16 a, __nv_bfloat16 b) {
    __nv_bfloat162 p; p.x = a; p.y = b;
    return *(uint32_t*)&p;
}

// SMEM layout (bytes). bf16 tiles, row stride 136 elements (272 B) -> conflict-free
#define SM_AH 0
#define SM_AL 34816
#define SM_BH 69632
#define SM_BL 104448
#define SM_SA 139264
#define SM_SB 140288
#define GEMM_SMEM 141312

// ---------------- CSR build ----------------
__global__ void k_zero() {
    int i = blockIdx.x * blockDim.x + threadIdx.x;
    if (i < N_NODES) g_cnt[i] = 0;
}
__global__ void k_hist(const int* __restrict__ dst) {
    for (int i = blockIdx.x * blockDim.x + threadIdx.x; i < N_EDGES;
         i += gridDim.x * blockDim.x)
        atomicAdd(&g_cnt[dst[i]], 1);
}
__global__ void k_scan() {
    __shared__ int part[1024];
    const int t  = threadIdx.x;
    const int CH = (N_NODES + 1023) / 1024;
    int base = t * CH;
    int s = 0;
    for (int i = 0; i < CH; i++) {
        int idx = base + i;
        if (idx < N_NODES) s += g_cnt[idx];
    }
    part[t] = s;
    __syncthreads();
    for (int d = 1; d < 1024; d <<= 1) {
        int v = (t >= d) ? part[t - d] : 0;
        __syncthreads();
        part[t] += v;
        __syncthreads();
    }
    int run = (t == 0) ? 0 : part[t - 1];
    for (int i = 0; i < CH; i++) {
        int idx = base + i;
        if (idx < N_NODES) { g_off[idx] = run; g_pos[idx] = run; run += g_cnt[idx]; }
    }
    if (t == 1023) g_off[N_NODES] = part[1023];
}
__global__ void k_fillcsr(const int* __restrict__ src, const int* __restrict__ dst) {
    for (int i = blockIdx.x * blockDim.x + threadIdx.x; i < N_EDGES;
         i += gridDim.x * blockDim.x) {
        int pos = atomicAdd(&g_pos[dst[i]], 1);
        g_csrc[pos] = src[i];
    }
}

// ---------------- embedding gather ----------------
__global__ void k_embed(const int* __restrict__ x, const float* __restrict__ emb) {
    int i = blockIdx.x * blockDim.x + threadIdx.x;
    if (i >= N_NODES * 32) return;
    int node = i >> 5, lane = i & 31;
    ((float4*)g_h)[i] = ((const float4*)emb)[x[node] * 32 + lane];
}

// ---------------- W prep: transpose + bf16 hi/lo split ----------------
__global__ void k_prepw(const float* __restrict__ Ws) {
    int i = blockIdx.x * blockDim.x + threadIdx.x;
    if (i >= 3 * 16384) return;
    int l = i / 16384, rem = i % 16384;
    int k = rem >> 7, n = rem & 127;
    float w = Ws[l * 16384 + k * 128 + n];
    __nv_bfloat16 hi = __float2bfloat16_rn(w);
    float res = w - __bfloat162float(hi);
    __nv_bfloat16 lo = __float2bfloat16_rn(res);
    g_wbh[(l * 128 + n) * 128 + k] = hi;   // B[n][k] = W[k][n]
    g_wbl[(l * 128 + n) * 128 + k] = lo;
}

// ---------------- bf16x3 tensor-core GEMM + fused scores ----------------
// CTA: 256 threads (8 warps), tile 128(M) x 128(N) x 128(K)
// warp grid 4(M) x 2(N): warp tile 32 x 64
__global__ __launch_bounds__(256, 1) void k_gemm(int layer,
                                                 const float* __restrict__ asrc,
                                                 const float* __restrict__ adst) {
    extern __shared__ char smem[];
    uint32_t sb = smem_u32(smem);
    const int tid  = threadIdx.x;
    const int wid  = tid >> 5;
    const int lane = tid & 31;
    const int wm   = wid & 3;
    const int wn   = wid >> 2;
    const int g    = lane >> 2;
    const int t    = lane & 3;
    const int rowbase = blockIdx.x * 128;

    // ---- load + convert A (fp32 -> bf16 hi/lo), load B (pre-split) ----
    const float4* Ag4 = (const float4*)g_h;
#pragma unroll
    for (int j = 0; j < 16; j++) {
        int idx = tid + j * 256;             // 4096 = 128 rows x 32 float4
        int r = idx >> 5, c4 = idx & 31;
        int gr = rowbase + r;
        float4 v = (gr < N_NODES) ? Ag4[gr * 32 + c4] : make_float4(0.f, 0.f, 0.f, 0.f);
        __nv_bfloat16 h0 = __float2bfloat16_rn(v.x);
        __nv_bfloat16 h1 = __float2bfloat16_rn(v.y);
        __nv_bfloat16 h2 = __float2bfloat16_rn(v.z);
        __nv_bfloat16 h3 = __float2bfloat16_rn(v.w);
        __nv_bfloat16 l0 = __float2bfloat16_rn(v.x - __bfloat162float(h0));
        __nv_bfloat16 l1 = __float2bfloat16_rn(v.y - __bfloat162float(h1));
        __nv_bfloat16 l2 = __float2bfloat16_rn(v.z - __bfloat162float(h2));
        __nv_bfloat16 l3 = __float2bfloat16_rn(v.w - __bfloat162float(h3));
        uint32_t off = (uint32_t)(r * 272 + c4 * 8);   // bytes
        *(uint2*)(smem + SM_AH + off) = make_uint2(bf2_bits(h0, h1), bf2_bits(h2, h3));
        *(uint2*)(smem + SM_AL + off) = make_uint2(bf2_bits(l0, l1), bf2_bits(l2, l3));
    }
    const uint4* wh4 = (const uint4*)(g_wbh + layer * 16384);
    const uint4* wl4 = (const uint4*)(g_wbl + layer * 16384);
#pragma unroll
    for (int j = 0; j < 8; j++) {
        int idx = tid + j * 256;             // 2048 = 128 rows x 16 uint4
        int r = idx >> 4, c8 = idx & 15;
        uint32_t off = (uint32_t)(r * 272 + c8 * 16);
        *(uint4*)(smem + SM_BH + off) = wh4[r * 16 + c8];
        *(uint4*)(smem + SM_BL + off) = wl4[r * 16 + c8];
    }
    __syncthreads();

    // ---- fragment base addresses (ldmatrix lane mapping) ----
    const int q  = lane >> 3;
    const int rr = lane & 7;
    // A: q0:(row rr, k0) q1:(row rr+8, k0) q2:(row rr, k0+8) q3:(row rr+8, k0+8)
    uint32_t aOff = (uint32_t)((wm * 32 + ((q & 1) << 3) + rr) * 272 + ((q >> 1) << 4));
    // B pair: q0:(n rr, k0) q1:(n rr, k0+8) q2:(n rr+8, k0) q3:(n rr+8, k0+8)
    uint32_t bOff = (uint32_t)((wn * 64 + ((q >> 1) << 3) + rr) * 272 + ((q & 1) << 4));
    uint32_t aH = sb + SM_AH + aOff, aL = sb + SM_AL + aOff;
    uint32_t bH = sb + SM_BH + bOff, bL = sb + SM_BL + bOff;

    float acc[2][8][4];
#pragma unroll
    for (int i = 0; i < 2; i++)
#pragma unroll
        for (int jn = 0; jn < 8; jn++)
#pragma unroll
            for (int c = 0; c < 4; c++) acc[i][jn][c] = 0.f;

    // ---- main K loop: 8 steps of k16 ----
#pragma unroll
    for (int ks = 0; ks < 8; ks++) {
        const uint32_t kb = ks * 32;
        uint32_t ah[2][4], al[2][4], b[4][4];
#pragma unroll
        for (int i = 0; i < 2; i++) {
            ldsm_x4(ah[i][0], ah[i][1], ah[i][2], ah[i][3], aH + kb + i * 4352);
            ldsm_x4(al[i][0], al[i][1], al[i][2], al[i][3], aL + kb + i * 4352);
        }
#pragma unroll
        for (int p = 0; p < 4; p++)
            ldsm_x4(b[p][0], b[p][1], b[p][2], b[p][3], bH + kb + p * 4352);
#pragma unroll
        for (int i = 0; i < 2; i++)
#pragma unroll
            for (int p = 0; p < 4; p++) {
                mma_bf16(acc[i][2 * p],     ah[i], b[p][0], b[p][1]);
                mma_bf16(acc[i][2 * p + 1], ah[i], b[p][2], b[p][3]);
            }
#pragma unroll
        for (int i = 0; i < 2; i++)
#pragma unroll
            for (int p = 0; p < 4; p++) {
                mma_bf16(acc[i][2 * p],     al[i], b[p][0], b[p][1]);
                mma_bf16(acc[i][2 * p + 1], al[i], b[p][2], b[p][3]);
            }
#pragma unroll
        for (int p = 0; p < 4; p++)
            ldsm_x4(b[p][0], b[p][1], b[p][2], b[p][3], bL + kb + p * 4352);
#pragma unroll
        for (int i = 0; i < 2; i++)
#pragma unroll
            for (int p = 0; p < 4; p++) {
                mma_bf16(acc[i][2 * p],     ah[i], b[p][0], b[p][1]);
                mma_bf16(acc[i][2 * p + 1], ah[i], b[p][2], b[p][3]);
            }
    }

    // ---- epilogue: store C + fused attention scores ----
    float sAr[2][2] = {{0.f, 0.f}, {0.f, 0.f}};
    float sBr[2][2] = {{0.f, 0.f}, {0.f, 0.f}};
#pragma unroll
    for (int jn = 0; jn < 8; jn++) {
        int col = wn * 64 + jn * 8 + 2 * t;
        float as0 = asrc[col], as1 = asrc[col + 1];
        float ad0 = adst[col], ad1 = adst[col + 1];
#pragma unroll
        for (int i = 0; i < 2; i++) {
            float* c = acc[i][jn];
            sAr[i][0] += c[0] * as0 + c[1] * as1;
            sAr[i][1] += c[2] * as0 + c[3] * as1;
            sBr[i][0] += c[0] * ad0 + c[1] * ad1;
            sBr[i][1] += c[2] * ad0 + c[3] * ad1;
            int row = rowbase + wm * 32 + i * 16 + g;
            if (row < N_NODES)
                *(float2*)&g_hw[row * 128 + col] = make_float2(c[0], c[1]);
            if (row + 8 < N_NODES)
                *(float2*)&g_hw[(row + 8) * 128 + col] = make_float2(c[2], c[3]);
        }
    }
#pragma unroll
    for (int off = 1; off <= 2; off <<= 1) {
#pragma unroll
        for (int i = 0; i < 2; i++)
#pragma unroll
            for (int h = 0; h < 2; h++) {
                sAr[i][h] += __shfl_xor_sync(0xffffffffu, sAr[i][h], off);
                sBr[i][h] += __shfl_xor_sync(0xffffffffu, sBr[i][h], off);
            }
    }
    float* sA2 = (float*)(smem + SM_SA);
    float* sB2 = (float*)(smem + SM_SB);
    if (t == 0) {
#pragma unroll
        for (int i = 0; i < 2; i++)
#pragma unroll
            for (int h = 0; h < 2; h++) {
                int rl = wm * 32 + i * 16 + h * 8 + g;
                sA2[wn * 128 + rl] = sAr[i][h];
                sB2[wn * 128 + rl] = sBr[i][h];
            }
    }
    __syncthreads();
    if (tid < 128) {
        int gr = rowbase + tid;
        if (gr < N_NODES) {
            g_ssrc[gr] = sA2[tid] + sA2[128 + tid];
            g_sdst[gr] = sB2[tid] + sB2[128 + tid];
        }
    }
}

// ---------------- per-node softmax aggregation (two-pass, warp per dst) ----------------
__global__ void k_agg(const float* __restrict__ bias, int relu) {
    int node = (blockIdx.x * blockDim.x + threadIdx.x) >> 5;
    int lane = threadIdx.x & 31;
    if (node >= N_NODES) return;

    const int beg = g_off[node];
    const int end = g_off[node + 1];
    const float sd = g_sdst[node];

    float m = -1e30f;
    for (int e = beg; e < end; e++) {
        float t = g_ssrc[g_csrc[e]] + sd;
        t = (t > 0.f) ? t : NEG_SLOPE * t;
        m = fmaxf(m, t);
    }
    float4 acc = make_float4(0.f, 0.f, 0.f, 0.f);
    float den = 0.f;
    const float4* hw4 = (const float4*)g_hw;
    for (int e = beg; e < end; e++) {
        int src = g_csrc[e];
        float t = g_ssrc[src] + sd;
        t = (t > 0.f) ? t : NEG_SLOPE * t;
        float w = __expf(t - m);
        den += w;
        float4 v = hw4[src * 32 + lane];
        acc.x += w * v.x; acc.y += w * v.y; acc.z += w * v.z; acc.w += w * v.w;
    }
    float inv = 1.f / den;
    float4 b = ((const float4*)bias)[lane];
    float4 o;
    o.x = acc.x * inv + b.x; o.y = acc.y * inv + b.y;
    o.z = acc.z * inv + b.z; o.w = acc.w * inv + b.w;
    if (relu) {
        o.x = fmaxf(o.x, 0.f); o.y = fmaxf(o.y, 0.f);
        o.z = fmaxf(o.z, 0.f); o.w = fmaxf(o.w, 0.f);
    }
    ((float4*)g_h)[node * 32 + lane] = o;
}

// ---------------- pooling + projection ----------------
__global__ void k_gbounds(const int* __restrict__ batch) {
    int g = threadIdx.x;
    if (g > N_GRAPHS) return;
    int lo = 0, hi = N_NODES;
    while (lo < hi) {
        int mid = (lo + hi) >> 1;
        if (batch[mid] < g) lo = mid + 1; else hi = mid;
    }
    g_gstart[g] = lo;
}
__global__ void k_pool() {
    int g = blockIdx.x;
    int c = threadIdx.x;
    int s = g_gstart[g], e = g_gstart[g + 1];
    float a0 = 0.f, a1 = 0.f, a2 = 0.f, a3 = 0.f;
    int i = s;
    for (; i + 3 < e; i += 4) {
        a0 += g_h[(i + 0) * HID + c];
        a1 += g_h[(i + 1) * HID + c];
        a2 += g_h[(i + 2) * HID + c];
        a3 += g_h[(i + 3) * HID + c];
    }
    for (; i < e; i++) a0 += g_h[i * HID + c];
    float cnt = (float)(e - s);
    g_pool[g * HID + c] = (a0 + a1 + a2 + a3) / fmaxf(cnt, 1.f);
}
__global__ void k_final(const float* __restrict__ Wout, const float* __restrict__ bout,
                        float* __restrict__ out) {
    int g = blockIdx.x;
    int o = threadIdx.x;
    float acc = 0.f;
#pragma unroll 4
    for (int c = 0; c < HID; c++)
        acc += g_pool[g * HID + c] * Wout[c * OUT_CH + o];
    out[g * OUT_CH + o] = acc + bout[o];
}

// ---------------- launch ----------------
extern "C" void kernel_launch(void* const* d_in, const int* in_sizes, int n_in,
                              void* d_out, int out_size) {
    const int*   x     = (const int*)  d_in[0];
    const int*   ei    = (const int*)  d_in[1];
    const int*   batch = (const int*)  d_in[2];
    const float* emb   = (const float*)d_in[3];
    const float* Ws    = (const float*)d_in[4];
    const float* asrc  = (const float*)d_in[5];
    const float* adst  = (const float*)d_in[6];
    const float* bs    = (const float*)d_in[7];
    const float* Wout  = (const float*)d_in[8];
    const float* bout  = (const float*)d_in[9];
    float* out = (float*)d_out;

    const int* src = ei;
    const int* dst = ei + N_EDGES;

    cudaFuncSetAttribute(k_gemm, cudaFuncAttributeMaxDynamicSharedMemorySize, GEMM_SMEM);

    k_zero<<<(N_NODES + 255) / 256, 256>>>();
    k_hist<<<1024, 256>>>(dst);
    k_prepw<<<(3 * 16384 + 255) / 256, 256>>>(Ws);
    k_scan<<<1, 1024>>>();
    k_fillcsr<<<1024, 256>>>(src, dst);
    k_embed<<<(N_NODES * 32 + 255) / 256, 256>>>(x, emb);

    const int gemm_blocks = (N_NODES + 127) / 128;   // 391
    const int warp_blocks = (N_NODES * 32 + 255) / 256;
    for (int l = 0; l < 3; l++) {
        k_gemm<<<gemm_blocks, 256, GEMM_SMEM>>>(l, asrc + l * HID, adst + l * HID);
        k_agg<<<warp_blocks, 256>>>(bs + l * HID, (l < 2) ? 1 : 0);
    }

    k_gbounds<<<1, 128>>>(batch);
    k_pool<<<N_GRAPHS, HID>>>();
    k_final<<<N_GRAPHS, OUT_CH>>>(Wout, bout, out);
}

// round 5
// speedup vs baseline: 1.6182x; 1.3169x over previous
#include <cuda_runtime.h>
#include <cuda_bf16.h>
#include <cstdint>

#define N_NODES   50000
#define N_EDGES   550000
#define HID       128
#define OUT_CH    64
#define N_GRAPHS  64
#define NEG_SLOPE 0.2f
#define SCAN_BLOCKS 50   // 50 * 1024 >= N_NODES

// ---------------- device scratch ----------------
__device__ float g_h [N_NODES * HID];
__device__ float g_hw[N_NODES * HID];
__device__ float g_ssrc[N_NODES];
__device__ float g_sdst[N_NODES];
__device__ int   g_cnt [N_NODES];
__device__ int   g_off [N_NODES + 1];
__device__ int   g_pos [N_NODES];
__device__ int   g_csrc[N_EDGES];
__device__ int   g_blksum[SCAN_BLOCKS];
__device__ int   g_blkoff[SCAN_BLOCKS];
__device__ int   g_gstart[N_GRAPHS + 1];
__device__ float g_pool[N_GRAPHS * HID];
// W transposed + bf16 hi/lo split: [3][128 n][128 k]
__device__ __nv_bfloat16 g_wbh[3 * 128 * 128];
__device__ __nv_bfloat16 g_wbl[3 * 128 * 128];

// ---------------- helpers ----------------
__device__ __forceinline__ uint32_t smem_u32(const void* p) {
    uint32_t a;
    asm("{ .reg .u64 t; cvta.to.shared.u64 t, %1; cvt.u32.u64 %0, t; }"
        : "=r"(a) : "l"(p));
    return a;
}
__device__ __forceinline__ void ldsm_x4(uint32_t& r0, uint32_t& r1,
                                        uint32_t& r2, uint32_t& r3, uint32_t addr) {
    asm volatile("ldmatrix.sync.aligned.m8n8.x4.shared.b16 {%0,%1,%2,%3}, [%4];"
                 : "=r"(r0), "=r"(r1), "=r"(r2), "=r"(r3) : "r"(addr));
}
__device__ __forceinline__ void mma_bf16(float* c, const uint32_t* a,
                                         uint32_t b0, uint32_t b1) {
    asm volatile(
        "mma.sync.aligned.m16n8k16.row.col.f32.bf16.bf16.f32 "
        "{%0,%1,%2,%3}, {%4,%5,%6,%7}, {%8,%9}, {%0,%1,%2,%3};"
        : "+f"(c[0]), "+f"(c[1]), "+f"(c[2]), "+f"(c[3])
        : "r"(a[0]), "r"(a[1]), "r"(a[2]), "r"(a[3]), "r"(b0), "r"(b1));
}
__device__ __forceinline__ uint32_t bf2_bits(__nv_bfloat16 a, __nv_bfloat16 b) {
    __nv_bfloat162 p; p.x = a; p.y = b;
    return *(uint32_t*)&p;
}

// SMEM layout (bytes). bf16 tiles, row stride 136 elements (272 B)
#define SM_AH 0
#define SM_AL 34816
#define SM_BH 69632
#define SM_BL 104448
#define SM_SA 139264
#define SM_SB 140288
#define GEMM_SMEM 141312

// ---------------- CSR build ----------------
__global__ void k_zero() {
    int i = blockIdx.x * blockDim.x + threadIdx.x;
    if (i < N_NODES) g_cnt[i] = 0;
}
__global__ void k_hist(const int* __restrict__ dst) {
    for (int i = blockIdx.x * blockDim.x + threadIdx.x; i < N_EDGES;
         i += gridDim.x * blockDim.x)
        atomicAdd(&g_cnt[dst[i]], 1);
}

// ---- two-level parallel scan ----
__global__ void k_scan1() {
    __shared__ int wsum[32];
    const int tid = threadIdx.x;
    const int i = blockIdx.x * 1024 + tid;
    const int lane = tid & 31, w = tid >> 5;
    int v = (i < N_NODES) ? g_cnt[i] : 0;
    int s = v;
#pragma unroll
    for (int off = 1; off < 32; off <<= 1) {
        int u = __shfl_up_sync(0xffffffffu, s, off);
        if (lane >= off) s += u;
    }
    if (lane == 31) wsum[w] = s;
    __syncthreads();
    if (w == 0) {
        int ws = wsum[lane];
#pragma unroll
        for (int off = 1; off < 32; off <<= 1) {
            int u = __shfl_up_sync(0xffffffffu, ws, off);
            if (lane >= off) ws += u;
        }
        wsum[lane] = ws;
    }
    __syncthreads();
    int excl = s - v + (w > 0 ? wsum[w - 1] : 0);
    if (i < N_NODES) g_off[i] = excl;
    if (tid == 1023) g_blksum[blockIdx.x] = wsum[31];
}

__global__ void k_scan2() {
    __shared__ int sm[SCAN_BLOCKS];
    int t = threadIdx.x;
    if (t < SCAN_BLOCKS) sm[t] = g_blksum[t];
    __syncthreads();
    if (t == 0) {
        int run = 0;
        for (int j = 0; j < SCAN_BLOCKS; j++) {
            int c = sm[j]; sm[j] = run; run += c;
        }
        g_off[N_NODES] = run;
    }
    __syncthreads();
    if (t < SCAN_BLOCKS) g_blkoff[t] = sm[t];
}

__global__ void k_scan3() {
    int i = blockIdx.x * blockDim.x + threadIdx.x;
    if (i >= N_NODES) return;
    int o = g_off[i] + g_blkoff[i >> 10];
    g_off[i] = o;
    g_pos[i] = o;
}

__global__ void k_fillcsr(const int* __restrict__ src, const int* __restrict__ dst) {
    for (int i = blockIdx.x * blockDim.x + threadIdx.x; i < N_EDGES;
         i += gridDim.x * blockDim.x) {
        int pos = atomicAdd(&g_pos[dst[i]], 1);
        g_csrc[pos] = src[i];
    }
}

// ---------------- embedding gather ----------------
__global__ void k_embed(const int* __restrict__ x, const float* __restrict__ emb) {
    int i = blockIdx.x * blockDim.x + threadIdx.x;
    if (i >= N_NODES * 32) return;
    int node = i >> 5, lane = i & 31;
    ((float4*)g_h)[i] = ((const float4*)emb)[x[node] * 32 + lane];
}

// ---------------- W prep: transpose + bf16 hi/lo split ----------------
__global__ void k_prepw(const float* __restrict__ Ws) {
    int i = blockIdx.x * blockDim.x + threadIdx.x;
    if (i >= 3 * 16384) return;
    int l = i / 16384, rem = i % 16384;
    int k = rem >> 7, n = rem & 127;
    float w = Ws[l * 16384 + k * 128 + n];
    __nv_bfloat16 hi = __float2bfloat16_rn(w);
    float res = w - __bfloat162float(hi);
    __nv_bfloat16 lo = __float2bfloat16_rn(res);
    g_wbh[(l * 128 + n) * 128 + k] = hi;   // B[n][k] = W[k][n]
    g_wbl[(l * 128 + n) * 128 + k] = lo;
}

// ---------------- bf16x3 tensor-core GEMM + fused scores ----------------
__global__ __launch_bounds__(256, 1) void k_gemm(int layer,
                                                 const float* __restrict__ asrc,
                                                 const float* __restrict__ adst) {
    extern __shared__ char smem[];
    uint32_t sb = smem_u32(smem);
    const int tid  = threadIdx.x;
    const int wid  = tid >> 5;
    const int lane = tid & 31;
    const int wm   = wid & 3;
    const int wn   = wid >> 2;
    const int g    = lane >> 2;
    const int t    = lane & 3;
    const int rowbase = blockIdx.x * 128;

    const float4* Ag4 = (const float4*)g_h;
#pragma unroll
    for (int j = 0; j < 16; j++) {
        int idx = tid + j * 256;
        int r = idx >> 5, c4 = idx & 31;
        int gr = rowbase + r;
        float4 v = (gr < N_NODES) ? Ag4[gr * 32 + c4] : make_float4(0.f, 0.f, 0.f, 0.f);
        __nv_bfloat16 h0 = __float2bfloat16_rn(v.x);
        __nv_bfloat16 h1 = __float2bfloat16_rn(v.y);
        __nv_bfloat16 h2 = __float2bfloat16_rn(v.z);
        __nv_bfloat16 h3 = __float2bfloat16_rn(v.w);
        __nv_bfloat16 l0 = __float2bfloat16_rn(v.x - __bfloat162float(h0));
        __nv_bfloat16 l1 = __float2bfloat16_rn(v.y - __bfloat162float(h1));
        __nv_bfloat16 l2 = __float2bfloat16_rn(v.z - __bfloat162float(h2));
        __nv_bfloat16 l3 = __float2bfloat16_rn(v.w - __bfloat162float(h3));
        uint32_t off = (uint32_t)(r * 272 + c4 * 8);
        *(uint2*)(smem + SM_AH + off) = make_uint2(bf2_bits(h0, h1), bf2_bits(h2, h3));
        *(uint2*)(smem + SM_AL + off) = make_uint2(bf2_bits(l0, l1), bf2_bits(l2, l3));
    }
    const uint4* wh4 = (const uint4*)(g_wbh + layer * 16384);
    const uint4* wl4 = (const uint4*)(g_wbl + layer * 16384);
#pragma unroll
    for (int j = 0; j < 8; j++) {
        int idx = tid + j * 256;
        int r = idx >> 4, c8 = idx & 15;
        uint32_t off = (uint32_t)(r * 272 + c8 * 16);
        *(uint4*)(smem + SM_BH + off) = wh4[r * 16 + c8];
        *(uint4*)(smem + SM_BL + off) = wl4[r * 16 + c8];
    }
    __syncthreads();

    const int q  = lane >> 3;
    const int rr = lane & 7;
    uint32_t aOff = (uint32_t)((wm * 32 + ((q & 1) << 3) + rr) * 272 + ((q >> 1) << 4));
    uint32_t bOff = (uint32_t)((wn * 64 + ((q >> 1) << 3) + rr) * 272 + ((q & 1) << 4));
    uint32_t aH = sb + SM_AH + aOff, aL = sb + SM_AL + aOff;
    uint32_t bH = sb + SM_BH + bOff, bL = sb + SM_BL + bOff;

    float acc[2][8][4];
#pragma unroll
    for (int i = 0; i < 2; i++)
#pragma unroll
        for (int jn = 0; jn < 8; jn++)
#pragma unroll
            for (int c = 0; c < 4; c++) acc[i][jn][c] = 0.f;

#pragma unroll
    for (int ks = 0; ks < 8; ks++) {
        const uint32_t kb = ks * 32;
        uint32_t ah[2][4], al[2][4], b[4][4];
#pragma unroll
        for (int i = 0; i < 2; i++) {
            ldsm_x4(ah[i][0], ah[i][1], ah[i][2], ah[i][3], aH + kb + i * 4352);
            ldsm_x4(al[i][0], al[i][1], al[i][2], al[i][3], aL + kb + i * 4352);
        }
#pragma unroll
        for (int p = 0; p < 4; p++)
            ldsm_x4(b[p][0], b[p][1], b[p][2], b[p][3], bH + kb + p * 4352);
#pragma unroll
        for (int i = 0; i < 2; i++)
#pragma unroll
            for (int p = 0; p < 4; p++) {
                mma_bf16(acc[i][2 * p],     ah[i], b[p][0], b[p][1]);
                mma_bf16(acc[i][2 * p + 1], ah[i], b[p][2], b[p][3]);
            }
#pragma unroll
        for (int i = 0; i < 2; i++)
#pragma unroll
            for (int p = 0; p < 4; p++) {
                mma_bf16(acc[i][2 * p],     al[i], b[p][0], b[p][1]);
                mma_bf16(acc[i][2 * p + 1], al[i], b[p][2], b[p][3]);
            }
#pragma unroll
        for (int p = 0; p < 4; p++)
            ldsm_x4(b[p][0], b[p][1], b[p][2], b[p][3], bL + kb + p * 4352);
#pragma unroll
        for (int i = 0; i < 2; i++)
#pragma unroll
            for (int p = 0; p < 4; p++) {
                mma_bf16(acc[i][2 * p],     ah[i], b[p][0], b[p][1]);
                mma_bf16(acc[i][2 * p + 1], ah[i], b[p][2], b[p][3]);
            }
    }

    float sAr[2][2] = {{0.f, 0.f}, {0.f, 0.f}};
    float sBr[2][2] = {{0.f, 0.f}, {0.f, 0.f}};
#pragma unroll
    for (int jn = 0; jn < 8; jn++) {
        int col = wn * 64 + jn * 8 + 2 * t;
        float as0 = asrc[col], as1 = asrc[col + 1];
        float ad0 = adst[col], ad1 = adst[col + 1];
#pragma unroll
        for (int i = 0; i < 2; i++) {
            float* c = acc[i][jn];
            sAr[i][0] += c[0] * as0 + c[1] * as1;
            sAr[i][1] += c[2] * as0 + c[3] * as1;
            sBr[i][0] += c[0] * ad0 + c[1] * ad1;
            sBr[i][1] += c[2] * ad0 + c[3] * ad1;
            int row = rowbase + wm * 32 + i * 16 + g;
            if (row < N_NODES)
                *(float2*)&g_hw[row * 128 + col] = make_float2(c[0], c[1]);
            if (row + 8 < N_NODES)
                *(float2*)&g_hw[(row + 8) * 128 + col] = make_float2(c[2], c[3]);
        }
    }
#pragma unroll
    for (int off = 1; off <= 2; off <<= 1) {
#pragma unroll
        for (int i = 0; i < 2; i++)
#pragma unroll
            for (int h = 0; h < 2; h++) {
                sAr[i][h] += __shfl_xor_sync(0xffffffffu, sAr[i][h], off);
                sBr[i][h] += __shfl_xor_sync(0xffffffffu, sBr[i][h], off);
            }
    }
    float* sA2 = (float*)(smem + SM_SA);
    float* sB2 = (float*)(smem + SM_SB);
    if (t == 0) {
#pragma unroll
        for (int i = 0; i < 2; i++)
#pragma unroll
            for (int h = 0; h < 2; h++) {
                int rl = wm * 32 + i * 16 + h * 8 + g;
                sA2[wn * 128 + rl] = sAr[i][h];
                sB2[wn * 128 + rl] = sBr[i][h];
            }
    }
    __syncthreads();
    if (tid < 128) {
        int gr = rowbase + tid;
        if (gr < N_NODES) {
            g_ssrc[gr] = sA2[tid] + sA2[128 + tid];
            g_sdst[gr] = sB2[tid] + sB2[128 + tid];
        }
    }
}

// ---------------- per-node softmax aggregation (two-pass, warp per dst) ----------------
__global__ void k_agg(const float* __restrict__ bias, int relu) {
    int node = (blockIdx.x * blockDim.x + threadIdx.x) >> 5;
    int lane = threadIdx.x & 31;
    if (node >= N_NODES) return;

    const int beg = g_off[node];
    const int end = g_off[node + 1];
    const float sd = g_sdst[node];

    float m = -1e30f;
    for (int e = beg; e < end; e++) {
        float t = g_ssrc[g_csrc[e]] + sd;
        t = (t > 0.f) ? t : NEG_SLOPE * t;
        m = fmaxf(m, t);
    }
    float4 acc = make_float4(0.f, 0.f, 0.f, 0.f);
    float den = 0.f;
    const float4* hw4 = (const float4*)g_hw;
    for (int e = beg; e < end; e++) {
        int src = g_csrc[e];
        float t = g_ssrc[src] + sd;
        t = (t > 0.f) ? t : NEG_SLOPE * t;
        float w = __expf(t - m);
        den += w;
        float4 v = hw4[src * 32 + lane];
        acc.x += w * v.x; acc.y += w * v.y; acc.z += w * v.z; acc.w += w * v.w;
    }
    float inv = 1.f / den;
    float4 b = ((const float4*)bias)[lane];
    float4 o;
    o.x = acc.x * inv + b.x; o.y = acc.y * inv + b.y;
    o.z = acc.z * inv + b.z; o.w = acc.w * inv + b.w;
    if (relu) {
        o.x = fmaxf(o.x, 0.f); o.y = fmaxf(o.y, 0.f);
        o.z = fmaxf(o.z, 0.f); o.w = fmaxf(o.w, 0.f);
    }
    ((float4*)g_h)[node * 32 + lane] = o;
}

// ---------------- pooling + projection ----------------
__global__ void k_gbounds(const int* __restrict__ batch) {
    int g = threadIdx.x;
    if (g > N_GRAPHS) return;
    int lo = 0, hi = N_NODES;
    while (lo < hi) {
        int mid = (lo + hi) >> 1;
        if (batch[mid] < g) lo = mid + 1; else hi = mid;
    }
    g_gstart[g] = lo;
}
__global__ void k_pool() {
    int g = blockIdx.x;
    int c = threadIdx.x;
    int s = g_gstart[g], e = g_gstart[g + 1];
    float a0 = 0.f, a1 = 0.f, a2 = 0.f, a3 = 0.f;
    int i = s;
    for (; i + 3 < e; i += 4) {
        a0 += g_h[(i + 0) * HID + c];
        a1 += g_h[(i + 1) * HID + c];
        a2 += g_h[(i + 2) * HID + c];
        a3 += g_h[(i + 3) * HID + c];
    }
    for (; i < e; i++) a0 += g_h[i * HID + c];
    float cnt = (float)(e - s);
    g_pool[g * HID + c] = (a0 + a1 + a2 + a3) / fmaxf(cnt, 1.f);
}
__global__ void k_final(const float* __restrict__ Wout, const float* __restrict__ bout,
                        float* __restrict__ out) {
    int g = blockIdx.x;
    int o = threadIdx.x;
    float acc = 0.f;
#pragma unroll 4
    for (int c = 0; c < HID; c++)
        acc += g_pool[g * HID + c] * Wout[c * OUT_CH + o];
    out[g * OUT_CH + o] = acc + bout[o];
}

// ---------------- launch ----------------
extern "C" void kernel_launch(void* const* d_in, const int* in_sizes, int n_in,
                              void* d_out, int out_size) {
    const int*   x     = (const int*)  d_in[0];
    const int*   ei    = (const int*)  d_in[1];
    const int*   batch = (const int*)  d_in[2];
    const float* emb   = (const float*)d_in[3];
    const float* Ws    = (const float*)d_in[4];
    const float* asrc  = (const float*)d_in[5];
    const float* adst  = (const float*)d_in[6];
    const float* bs    = (const float*)d_in[7];
    const float* Wout  = (const float*)d_in[8];
    const float* bout  = (const float*)d_in[9];
    float* out = (float*)d_out;

    const int* src = ei;
    const int* dst = ei + N_EDGES;

    cudaFuncSetAttribute(k_gemm, cudaFuncAttributeMaxDynamicSharedMemorySize, GEMM_SMEM);

    k_zero<<<(N_NODES + 255) / 256, 256>>>();
    k_hist<<<1024, 256>>>(dst);
    k_prepw<<<(3 * 16384 + 255) / 256, 256>>>(Ws);
    k_scan1<<<SCAN_BLOCKS, 1024>>>();
    k_scan2<<<1, 64>>>();
    k_scan3<<<(N_NODES + 255) / 256, 256>>>();
    k_fillcsr<<<1024, 256>>>(src, dst);
    k_embed<<<(N_NODES * 32 + 255) / 256, 256>>>(x, emb);

    const int gemm_blocks = (N_NODES + 127) / 128;
    const int warp_blocks = (N_NODES * 32 + 255) / 256;
    for (int l = 0; l < 3; l++) {
        k_gemm<<<gemm_blocks, 256, GEMM_SMEM>>>(l, asrc + l * HID, adst + l * HID);
        k_agg<<<warp_blocks, 256>>>(bs + l * HID, (l < 2) ? 1 : 0);
    }

    k_gbounds<<<1, 128>>>(batch);
    k_pool<<<N_GRAPHS, HID>>>();
    k_final<<<N_GRAPHS, OUT_CH>>>(Wout, bout, out);
}

// round 6
// speedup vs baseline: 1.6299x; 1.0072x over previous
#include <cuda_runtime.h>
#include <cuda_bf16.h>
#include <cstdint>

#define N_NODES   50000
#define N_EDGES   550000
#define HID       128
#define OUT_CH    64
#define N_GRAPHS  64
#define NEG_SLOPE 0.2f
#define SCAN_BLOCKS 50   // 50 * 1024 >= N_NODES

// ---------------- device scratch ----------------
__device__ float g_h [N_NODES * HID];
__device__ float g_hw[N_NODES * HID];
__device__ float g_ssrc[N_NODES];
__device__ float g_sdst[N_NODES];
__device__ int   g_cnt [N_NODES];
__device__ int   g_off [N_NODES + 1];
__device__ int   g_pos [N_NODES];
__device__ int   g_csrc[N_EDGES];
__device__ int   g_blksum[SCAN_BLOCKS];
__device__ int   g_blkoff[SCAN_BLOCKS];
__device__ int   g_gstart[N_GRAPHS + 1];
__device__ float g_pool[N_GRAPHS * HID];
// W transposed + bf16 hi/lo split: [3][128 n][128 k]
__device__ __nv_bfloat16 g_wbh[3 * 128 * 128];
__device__ __nv_bfloat16 g_wbl[3 * 128 * 128];

// ---------------- helpers ----------------
__device__ __forceinline__ uint32_t smem_u32(const void* p) {
    uint32_t a;
    asm("{ .reg .u64 t; cvta.to.shared.u64 t, %1; cvt.u32.u64 %0, t; }"
        : "=r"(a) : "l"(p));
    return a;
}
__device__ __forceinline__ void ldsm_x4(uint32_t& r0, uint32_t& r1,
                                        uint32_t& r2, uint32_t& r3, uint32_t addr) {
    asm volatile("ldmatrix.sync.aligned.m8n8.x4.shared.b16 {%0,%1,%2,%3}, [%4];"
                 : "=r"(r0), "=r"(r1), "=r"(r2), "=r"(r3) : "r"(addr));
}
__device__ __forceinline__ void mma_bf16(float* c, const uint32_t* a,
                                         uint32_t b0, uint32_t b1) {
    asm volatile(
        "mma.sync.aligned.m16n8k16.row.col.f32.bf16.bf16.f32 "
        "{%0,%1,%2,%3}, {%4,%5,%6,%7}, {%8,%9}, {%0,%1,%2,%3};"
        : "+f"(c[0]), "+f"(c[1]), "+f"(c[2]), "+f"(c[3])
        : "r"(a[0]), "r"(a[1]), "r"(a[2]), "r"(a[3]), "r"(b0), "r"(b1));
}
__device__ __forceinline__ uint32_t bf2_bits(__nv_bfloat16 a, __nv_bfloat16 b) {
    __nv_bfloat162 p; p.x = a; p.y = b;
    return *(uint32_t*)&p;
}

// SMEM layout (bytes). bf16 tiles, row stride 136 elements (272 B)
#define SM_AH 0
#define SM_AL 34816
#define SM_BH 69632
#define SM_BL 104448
#define SM_SA 139264
#define SM_SB 140288
#define GEMM_SMEM 141312

// ---------------- CSR build ----------------
__global__ void k_zero() {
    int i = blockIdx.x * blockDim.x + threadIdx.x;
    if (i < N_NODES) g_cnt[i] = 0;
}
__global__ void k_hist(const int* __restrict__ dst) {
    for (int i = blockIdx.x * blockDim.x + threadIdx.x; i < N_EDGES;
         i += gridDim.x * blockDim.x)
        atomicAdd(&g_cnt[dst[i]], 1);
}

// ---- two-level parallel scan ----
__global__ void k_scan1() {
    __shared__ int wsum[32];
    const int tid = threadIdx.x;
    const int i = blockIdx.x * 1024 + tid;
    const int lane = tid & 31, w = tid >> 5;
    int v = (i < N_NODES) ? g_cnt[i] : 0;
    int s = v;
#pragma unroll
    for (int off = 1; off < 32; off <<= 1) {
        int u = __shfl_up_sync(0xffffffffu, s, off);
        if (lane >= off) s += u;
    }
    if (lane == 31) wsum[w] = s;
    __syncthreads();
    if (w == 0) {
        int ws = wsum[lane];
#pragma unroll
        for (int off = 1; off < 32; off <<= 1) {
            int u = __shfl_up_sync(0xffffffffu, ws, off);
            if (lane >= off) ws += u;
        }
        wsum[lane] = ws;
    }
    __syncthreads();
    int excl = s - v + (w > 0 ? wsum[w - 1] : 0);
    if (i < N_NODES) g_off[i] = excl;
    if (tid == 1023) g_blksum[blockIdx.x] = wsum[31];
}

__global__ void k_scan2() {
    __shared__ int sm[SCAN_BLOCKS];
    int t = threadIdx.x;
    if (t < SCAN_BLOCKS) sm[t] = g_blksum[t];
    __syncthreads();
    if (t == 0) {
        int run = 0;
        for (int j = 0; j < SCAN_BLOCKS; j++) {
            int c = sm[j]; sm[j] = run; run += c;
        }
        g_off[N_NODES] = run;
    }
    __syncthreads();
    if (t < SCAN_BLOCKS) g_blkoff[t] = sm[t];
}

__global__ void k_scan3() {
    int i = blockIdx.x * blockDim.x + threadIdx.x;
    if (i >= N_NODES) return;
    int o = g_off[i] + g_blkoff[i >> 10];
    g_off[i] = o;
    g_pos[i] = o;
}

__global__ void k_fillcsr(const int* __restrict__ src, const int* __restrict__ dst) {
    for (int i = blockIdx.x * blockDim.x + threadIdx.x; i < N_EDGES;
         i += gridDim.x * blockDim.x) {
        int pos = atomicAdd(&g_pos[dst[i]], 1);
        g_csrc[pos] = src[i];
    }
}

// ---------------- embedding gather ----------------
__global__ void k_embed(const int* __restrict__ x, const float* __restrict__ emb) {
    int i = blockIdx.x * blockDim.x + threadIdx.x;
    if (i >= N_NODES * 32) return;
    int node = i >> 5, lane = i & 31;
    ((float4*)g_h)[i] = ((const float4*)emb)[x[node] * 32 + lane];
}

// ---------------- W prep: transpose + bf16 hi/lo split ----------------
__global__ void k_prepw(const float* __restrict__ Ws) {
    int i = blockIdx.x * blockDim.x + threadIdx.x;
    if (i >= 3 * 16384) return;
    int l = i / 16384, rem = i % 16384;
    int k = rem >> 7, n = rem & 127;
    float w = Ws[l * 16384 + k * 128 + n];
    __nv_bfloat16 hi = __float2bfloat16_rn(w);
    float res = w - __bfloat162float(hi);
    __nv_bfloat16 lo = __float2bfloat16_rn(res);
    g_wbh[(l * 128 + n) * 128 + k] = hi;   // B[n][k] = W[k][n]
    g_wbl[(l * 128 + n) * 128 + k] = lo;
}

// ---------------- bf16x3 tensor-core GEMM + fused scores ----------------
__global__ __launch_bounds__(256, 1) void k_gemm(int layer,
                                                 const float* __restrict__ asrc,
                                                 const float* __restrict__ adst) {
    extern __shared__ char smem[];
    uint32_t sb = smem_u32(smem);
    const int tid  = threadIdx.x;
    const int wid  = tid >> 5;
    const int lane = tid & 31;
    const int wm   = wid & 3;
    const int wn   = wid >> 2;
    const int g    = lane >> 2;
    const int t    = lane & 3;
    const int rowbase = blockIdx.x * 128;

    const float4* Ag4 = (const float4*)g_h;
#pragma unroll
    for (int j = 0; j < 16; j++) {
        int idx = tid + j * 256;
        int r = idx >> 5, c4 = idx & 31;
        int gr = rowbase + r;
        float4 v = (gr < N_NODES) ? Ag4[gr * 32 + c4] : make_float4(0.f, 0.f, 0.f, 0.f);
        __nv_bfloat16 h0 = __float2bfloat16_rn(v.x);
        __nv_bfloat16 h1 = __float2bfloat16_rn(v.y);
        __nv_bfloat16 h2 = __float2bfloat16_rn(v.z);
        __nv_bfloat16 h3 = __float2bfloat16_rn(v.w);
        __nv_bfloat16 l0 = __float2bfloat16_rn(v.x - __bfloat162float(h0));
        __nv_bfloat16 l1 = __float2bfloat16_rn(v.y - __bfloat162float(h1));
        __nv_bfloat16 l2 = __float2bfloat16_rn(v.z - __bfloat162float(h2));
        __nv_bfloat16 l3 = __float2bfloat16_rn(v.w - __bfloat162float(h3));
        uint32_t off = (uint32_t)(r * 272 + c4 * 8);
        *(uint2*)(smem + SM_AH + off) = make_uint2(bf2_bits(h0, h1), bf2_bits(h2, h3));
        *(uint2*)(smem + SM_AL + off) = make_uint2(bf2_bits(l0, l1), bf2_bits(l2, l3));
    }
    const uint4* wh4 = (const uint4*)(g_wbh + layer * 16384);
    const uint4* wl4 = (const uint4*)(g_wbl + layer * 16384);
#pragma unroll
    for (int j = 0; j < 8; j++) {
        int idx = tid + j * 256;
        int r = idx >> 4, c8 = idx & 15;
        uint32_t off = (uint32_t)(r * 272 + c8 * 16);
        *(uint4*)(smem + SM_BH + off) = wh4[r * 16 + c8];
        *(uint4*)(smem + SM_BL + off) = wl4[r * 16 + c8];
    }
    __syncthreads();

    const int q  = lane >> 3;
    const int rr = lane & 7;
    uint32_t aOff = (uint32_t)((wm * 32 + ((q & 1) << 3) + rr) * 272 + ((q >> 1) << 4));
    uint32_t bOff = (uint32_t)((wn * 64 + ((q >> 1) << 3) + rr) * 272 + ((q & 1) << 4));
    uint32_t aH = sb + SM_AH + aOff, aL = sb + SM_AL + aOff;
    uint32_t bH = sb + SM_BH + bOff, bL = sb + SM_BL + bOff;

    float acc[2][8][4];
#pragma unroll
    for (int i = 0; i < 2; i++)
#pragma unroll
        for (int jn = 0; jn < 8; jn++)
#pragma unroll
            for (int c = 0; c < 4; c++) acc[i][jn][c] = 0.f;

#pragma unroll
    for (int ks = 0; ks < 8; ks++) {
        const uint32_t kb = ks * 32;
        uint32_t ah[2][4], al[2][4], b[4][4];
#pragma unroll
        for (int i = 0; i < 2; i++) {
            ldsm_x4(ah[i][0], ah[i][1], ah[i][2], ah[i][3], aH + kb + i * 4352);
            ldsm_x4(al[i][0], al[i][1], al[i][2], al[i][3], aL + kb + i * 4352);
        }
#pragma unroll
        for (int p = 0; p < 4; p++)
            ldsm_x4(b[p][0], b[p][1], b[p][2], b[p][3], bH + kb + p * 4352);
#pragma unroll
        for (int i = 0; i < 2; i++)
#pragma unroll
            for (int p = 0; p < 4; p++) {
                mma_bf16(acc[i][2 * p],     ah[i], b[p][0], b[p][1]);
                mma_bf16(acc[i][2 * p + 1], ah[i], b[p][2], b[p][3]);
            }
#pragma unroll
        for (int i = 0; i < 2; i++)
#pragma unroll
            for (int p = 0; p < 4; p++) {
                mma_bf16(acc[i][2 * p],     al[i], b[p][0], b[p][1]);
                mma_bf16(acc[i][2 * p + 1], al[i], b[p][2], b[p][3]);
            }
#pragma unroll
        for (int p = 0; p < 4; p++)
            ldsm_x4(b[p][0], b[p][1], b[p][2], b[p][3], bL + kb + p * 4352);
#pragma unroll
        for (int i = 0; i < 2; i++)
#pragma unroll
            for (int p = 0; p < 4; p++) {
                mma_bf16(acc[i][2 * p],     ah[i], b[p][0], b[p][1]);
                mma_bf16(acc[i][2 * p + 1], ah[i], b[p][2], b[p][3]);
            }
    }

    float sAr[2][2] = {{0.f, 0.f}, {0.f, 0.f}};
    float sBr[2][2] = {{0.f, 0.f}, {0.f, 0.f}};
#pragma unroll
    for (int jn = 0; jn < 8; jn++) {
        int col = wn * 64 + jn * 8 + 2 * t;
        float as0 = asrc[col], as1 = asrc[col + 1];
        float ad0 = adst[col], ad1 = adst[col + 1];
#pragma unroll
        for (int i = 0; i < 2; i++) {
            float* c = acc[i][jn];
            sAr[i][0] += c[0] * as0 + c[1] * as1;
            sAr[i][1] += c[2] * as0 + c[3] * as1;
            sBr[i][0] += c[0] * ad0 + c[1] * ad1;
            sBr[i][1] += c[2] * ad0 + c[3] * ad1;
            int row = rowbase + wm * 32 + i * 16 + g;
            if (row < N_NODES)
                *(float2*)&g_hw[row * 128 + col] = make_float2(c[0], c[1]);
            if (row + 8 < N_NODES)
                *(float2*)&g_hw[(row + 8) * 128 + col] = make_float2(c[2], c[3]);
        }
    }
#pragma unroll
    for (int off = 1; off <= 2; off <<= 1) {
#pragma unroll
        for (int i = 0; i < 2; i++)
#pragma unroll
            for (int h = 0; h < 2; h++) {
                sAr[i][h] += __shfl_xor_sync(0xffffffffu, sAr[i][h], off);
                sBr[i][h] += __shfl_xor_sync(0xffffffffu, sBr[i][h], off);
            }
    }
    float* sA2 = (float*)(smem + SM_SA);
    float* sB2 = (float*)(smem + SM_SB);
    if (t == 0) {
#pragma unroll
        for (int i = 0; i < 2; i++)
#pragma unroll
            for (int h = 0; h < 2; h++) {
                int rl = wm * 32 + i * 16 + h * 8 + g;
                sA2[wn * 128 + rl] = sAr[i][h];
                sB2[wn * 128 + rl] = sBr[i][h];
            }
    }
    __syncthreads();
    if (tid < 128) {
        int gr = rowbase + tid;
        if (gr < N_NODES) {
            g_ssrc[gr] = sA2[tid] + sA2[128 + tid];
            g_sdst[gr] = sB2[tid] + sB2[128 + tid];
        }
    }
}

// ---------------- single-pass online-softmax aggregation ----------------
// warp per dst node; 32 edges per chunk lane-parallel; weights via shfl
__global__ void k_agg(const float* __restrict__ bias, int relu) {
    int node = (blockIdx.x * blockDim.x + threadIdx.x) >> 5;
    int lane = threadIdx.x & 31;
    if (node >= N_NODES) return;

    const int beg = g_off[node];
    const int end = g_off[node + 1];
    const float sd = g_sdst[node];
    const float4* hw4 = (const float4*)g_hw;

    float m = -1e30f;
    float denl = 0.f;                     // per-lane denom partial
    float4 acc = make_float4(0.f, 0.f, 0.f, 0.f);

    for (int base = beg; base < end; base += 32) {
        int e = base + lane;
        bool valid = (e < end);
        int srcr = valid ? g_csrc[e] : 0;
        float tt = -1e30f;
        if (valid) {
            float s = g_ssrc[srcr] + sd;
            tt = (s > 0.f) ? s : NEG_SLOPE * s;
        }
        // chunk max
        float mc = tt;
#pragma unroll
        for (int off = 16; off > 0; off >>= 1)
            mc = fmaxf(mc, __shfl_xor_sync(0xffffffffu, mc, off));
        if (mc > m) {                     // warp-uniform
            float f = __expf(m - mc);     // first chunk: exp(-inf)=0, acc already 0
            denl *= f;
            acc.x *= f; acc.y *= f; acc.z *= f; acc.w *= f;
            m = mc;
        }
        float w = valid ? __expf(tt - m) : 0.f;
        denl += w;
        int n = end - base; if (n > 32) n = 32;
        for (int j = 0; j < n; j++) {
            float wj = __shfl_sync(0xffffffffu, w, j);
            int   sj = __shfl_sync(0xffffffffu, srcr, j);
            float4 v = hw4[sj * 32 + lane];
            acc.x += wj * v.x; acc.y += wj * v.y;
            acc.z += wj * v.z; acc.w += wj * v.w;
        }
    }
    // total denom
    float den = denl;
#pragma unroll
    for (int off = 16; off > 0; off >>= 1)
        den += __shfl_xor_sync(0xffffffffu, den, off);

    float inv = 1.f / den;
    float4 b = ((const float4*)bias)[lane];
    float4 o;
    o.x = acc.x * inv + b.x; o.y = acc.y * inv + b.y;
    o.z = acc.z * inv + b.z; o.w = acc.w * inv + b.w;
    if (relu) {
        o.x = fmaxf(o.x, 0.f); o.y = fmaxf(o.y, 0.f);
        o.z = fmaxf(o.z, 0.f); o.w = fmaxf(o.w, 0.f);
    }
    ((float4*)g_h)[node * 32 + lane] = o;
}

// ---------------- pooling + projection ----------------
__global__ void k_gbounds(const int* __restrict__ batch) {
    int g = threadIdx.x;
    if (g > N_GRAPHS) return;
    int lo = 0, hi = N_NODES;
    while (lo < hi) {
        int mid = (lo + hi) >> 1;
        if (batch[mid] < g) lo = mid + 1; else hi = mid;
    }
    g_gstart[g] = lo;
}
__global__ void k_pool() {
    int g = blockIdx.x;
    int c = threadIdx.x;
    int s = g_gstart[g], e = g_gstart[g + 1];
    float a0 = 0.f, a1 = 0.f, a2 = 0.f, a3 = 0.f;
    int i = s;
    for (; i + 3 < e; i += 4) {
        a0 += g_h[(i + 0) * HID + c];
        a1 += g_h[(i + 1) * HID + c];
        a2 += g_h[(i + 2) * HID + c];
        a3 += g_h[(i + 3) * HID + c];
    }
    for (; i < e; i++) a0 += g_h[i * HID + c];
    float cnt = (float)(e - s);
    g_pool[g * HID + c] = (a0 + a1 + a2 + a3) / fmaxf(cnt, 1.f);
}
__global__ void k_final(const float* __restrict__ Wout, const float* __restrict__ bout,
                        float* __restrict__ out) {
    int g = blockIdx.x;
    int o = threadIdx.x;
    float acc = 0.f;
#pragma unroll 4
    for (int c = 0; c < HID; c++)
        acc += g_pool[g * HID + c] * Wout[c * OUT_CH + o];
    out[g * OUT_CH + o] = acc + bout[o];
}

// ---------------- launch ----------------
extern "C" void kernel_launch(void* const* d_in, const int* in_sizes, int n_in,
                              void* d_out, int out_size) {
    const int*   x     = (const int*)  d_in[0];
    const int*   ei    = (const int*)  d_in[1];
    const int*   batch = (const int*)  d_in[2];
    const float* emb   = (const float*)d_in[3];
    const float* Ws    = (const float*)d_in[4];
    const float* asrc  = (const float*)d_in[5];
    const float* adst  = (const float*)d_in[6];
    const float* bs    = (const float*)d_in[7];
    const float* Wout  = (const float*)d_in[8];
    const float* bout  = (const float*)d_in[9];
    float* out = (float*)d_out;

    const int* src = ei;
    const int* dst = ei + N_EDGES;

    static cudaStream_t s1 = 0;
    static cudaEvent_t evFork = 0, evJoin = 0;
    static int inited = 0;
    if (!inited) {
        cudaStreamCreateWithFlags(&s1, cudaStreamNonBlocking);
        cudaEventCreateWithFlags(&evFork, cudaEventDisableTiming);
        cudaEventCreateWithFlags(&evJoin, cudaEventDisableTiming);
        cudaFuncSetAttribute(k_gemm, cudaFuncAttributeMaxDynamicSharedMemorySize, GEMM_SMEM);
        inited = 1;
    }

    // fork: CSR build on side stream, compute prologue on main stream
    cudaEventRecord(evFork, 0);
    cudaStreamWaitEvent(s1, evFork, 0);

    // side stream: CSR build + graph bounds
    k_zero<<<(N_NODES + 255) / 256, 256, 0, s1>>>();
    k_hist<<<1024, 256, 0, s1>>>(dst);
    k_scan1<<<SCAN_BLOCKS, 1024, 0, s1>>>();
    k_scan2<<<1, 64, 0, s1>>>();
    k_scan3<<<(N_NODES + 255) / 256, 256, 0, s1>>>();
    k_fillcsr<<<1024, 256, 0, s1>>>(src, dst);
    k_gbounds<<<1, 128, 0, s1>>>(batch);

    // main stream: W prep + embedding + layer-0 GEMM
    const int gemm_blocks = (N_NODES + 127) / 128;
    const int warp_blocks = (N_NODES * 32 + 255) / 256;
    k_prepw<<<(3 * 16384 + 255) / 256, 256>>>(Ws);
    k_embed<<<(N_NODES * 32 + 255) / 256, 256>>>(x, emb);
    k_gemm<<<gemm_blocks, 256, GEMM_SMEM>>>(0, asrc, adst);

    // join: agg needs CSR
    cudaEventRecord(evJoin, s1);
    cudaStreamWaitEvent(0, evJoin, 0);

    k_agg<<<warp_blocks, 256>>>(bs, 1);
    for (int l = 1; l < 3; l++) {
        k_gemm<<<gemm_blocks, 256, GEMM_SMEM>>>(l, asrc + l * HID, adst + l * HID);
        k_agg<<<warp_blocks, 256>>>(bs + l * HID, (l < 2) ? 1 : 0);
    }

    k_pool<<<N_GRAPHS, HID>>>();
    k_final<<<N_GRAPHS, OUT_CH>>>(Wout, bout, out);
}

// round 7
// speedup vs baseline: 1.6375x; 1.0047x over previous
#include <cuda_runtime.h>
#include <cuda_bf16.h>
#include <cuda_fp16.h>
#include <cstdint>

#define N_NODES   50000
#define N_EDGES   550000
#define HID       128
#define OUT_CH    64
#define N_GRAPHS  64
#define NEG_SLOPE 0.2f
#define SCAN_BLOCKS 50   // 50 * 1024 >= N_NODES

// ---------------- device scratch ----------------
__device__ float  g_h [N_NODES * HID];
__device__ __half g_hw[N_NODES * HID];     // fp16 features for edge gather
__device__ float  g_ssrc[N_NODES];
__device__ float  g_sdst[N_NODES];
__device__ int    g_cnt [N_NODES];
__device__ int    g_off [N_NODES + 1];
__device__ int    g_pos [N_NODES];
__device__ int    g_csrc[N_EDGES];
__device__ int    g_blksum[SCAN_BLOCKS];
__device__ int    g_gstart[N_GRAPHS + 1];
// W transposed + bf16 hi/lo split: [3][128 n][128 k]
__device__ __nv_bfloat16 g_wbh[3 * 128 * 128];
__device__ __nv_bfloat16 g_wbl[3 * 128 * 128];

// ---------------- helpers ----------------
__device__ __forceinline__ uint32_t smem_u32(const void* p) {
    uint32_t a;
    asm("{ .reg .u64 t; cvta.to.shared.u64 t, %1; cvt.u32.u64 %0, t; }"
        : "=r"(a) : "l"(p));
    return a;
}
__device__ __forceinline__ void ldsm_x4(uint32_t& r0, uint32_t& r1,
                                        uint32_t& r2, uint32_t& r3, uint32_t addr) {
    asm volatile("ldmatrix.sync.aligned.m8n8.x4.shared.b16 {%0,%1,%2,%3}, [%4];"
                 : "=r"(r0), "=r"(r1), "=r"(r2), "=r"(r3) : "r"(addr));
}
__device__ __forceinline__ void mma_bf16(float* c, const uint32_t* a,
                                         uint32_t b0, uint32_t b1) {
    asm volatile(
        "mma.sync.aligned.m16n8k16.row.col.f32.bf16.bf16.f32 "
        "{%0,%1,%2,%3}, {%4,%5,%6,%7}, {%8,%9}, {%0,%1,%2,%3};"
        : "+f"(c[0]), "+f"(c[1]), "+f"(c[2]), "+f"(c[3])
        : "r"(a[0]), "r"(a[1]), "r"(a[2]), "r"(a[3]), "r"(b0), "r"(b1));
}
__device__ __forceinline__ uint32_t bf2_bits(__nv_bfloat16 a, __nv_bfloat16 b) {
    __nv_bfloat162 p; p.x = a; p.y = b;
    return *(uint32_t*)&p;
}

// SMEM layout (bytes). bf16 tiles, row stride 136 elements (272 B)
#define SM_AH 0
#define SM_AL 34816
#define SM_BH 69632
#define SM_BL 104448
#define SM_SA 139264
#define SM_SB 140288
#define GEMM_SMEM 141312

// ---------------- CSR build ----------------
__global__ void k_zero() {
    int i = blockIdx.x * blockDim.x + threadIdx.x;
    if (i < N_NODES) g_cnt[i] = 0;
}
__global__ void k_hist(const int* __restrict__ dst) {
    for (int i = blockIdx.x * blockDim.x + threadIdx.x; i < N_EDGES;
         i += gridDim.x * blockDim.x)
        atomicAdd(&g_cnt[dst[i]], 1);
}

// ---- scan level 1: per-1024-chunk exclusive scan + chunk totals ----
__global__ void k_scan1() {
    __shared__ int wsum[32];
    const int tid = threadIdx.x;
    const int i = blockIdx.x * 1024 + tid;
    const int lane = tid & 31, w = tid >> 5;
    int v = (i < N_NODES) ? g_cnt[i] : 0;
    int s = v;
#pragma unroll
    for (int off = 1; off < 32; off <<= 1) {
        int u = __shfl_up_sync(0xffffffffu, s, off);
        if (lane >= off) s += u;
    }
    if (lane == 31) wsum[w] = s;
    __syncthreads();
    if (w == 0) {
        int ws = wsum[lane];
#pragma unroll
        for (int off = 1; off < 32; off <<= 1) {
            int u = __shfl_up_sync(0xffffffffu, ws, off);
            if (lane >= off) ws += u;
        }
        wsum[lane] = ws;
    }
    __syncthreads();
    int excl = s - v + (w > 0 ? wsum[w - 1] : 0);
    if (i < N_NODES) g_off[i] = excl;
    if (tid == 1023) g_blksum[blockIdx.x] = wsum[31];
}

// ---- scan level 2 + finalize + graph bounds, fused ----
// 256-thread blocks: i>>10 is block-constant -> warp 0 computes chunk offset.
__global__ void k_scan23(const int* __restrict__ batch) {
    __shared__ int s_off;
    const int tid = threadIdx.x;
    const int i = blockIdx.x * 256 + tid;
    const int chunk = (int)(blockIdx.x >> 2);     // = i >> 10 for all threads

    if (tid < 32) {
        int a = (tid < chunk) ? g_blksum[tid] : 0;
        int b = (tid + 32 < chunk) ? g_blksum[tid + 32] : 0;
        int s = a + b;
#pragma unroll
        for (int off = 16; off > 0; off >>= 1)
            s += __shfl_xor_sync(0xffffffffu, s, off);
        if (tid == 0) s_off = s;
    }
    __syncthreads();

    if (i < N_NODES) {
        int o = g_off[i] + s_off;
        g_off[i] = o;
        g_pos[i] = o;
    }
    if (blockIdx.x == 0) {
        if (tid == 0) {
            int tot = 0;
            for (int j = 0; j < SCAN_BLOCKS; j++) tot += g_blksum[j];
            g_off[N_NODES] = tot;
        }
        // graph bounds (binary search over sorted batch)
        if (tid >= 64 && tid <= 64 + N_GRAPHS) {
            int g = tid - 64;
            int lo = 0, hi = N_NODES;
            while (lo < hi) {
                int mid = (lo + hi) >> 1;
                if (batch[mid] < g) lo = mid + 1; else hi = mid;
            }
            g_gstart[g] = lo;
        }
    }
}

__global__ void k_fillcsr(const int* __restrict__ src, const int* __restrict__ dst) {
    for (int i = blockIdx.x * blockDim.x + threadIdx.x; i < N_EDGES;
         i += gridDim.x * blockDim.x) {
        int pos = atomicAdd(&g_pos[dst[i]], 1);
        g_csrc[pos] = src[i];
    }
}

// ---------------- embedding gather ----------------
__global__ void k_embed(const int* __restrict__ x, const float* __restrict__ emb) {
    int i = blockIdx.x * blockDim.x + threadIdx.x;
    if (i >= N_NODES * 32) return;
    int node = i >> 5, lane = i & 31;
    ((float4*)g_h)[i] = ((const float4*)emb)[x[node] * 32 + lane];
}

// ---------------- W prep: transpose + bf16 hi/lo split ----------------
__global__ void k_prepw(const float* __restrict__ Ws) {
    int i = blockIdx.x * blockDim.x + threadIdx.x;
    if (i >= 3 * 16384) return;
    int l = i / 16384, rem = i % 16384;
    int k = rem >> 7, n = rem & 127;
    float w = Ws[l * 16384 + k * 128 + n];
    __nv_bfloat16 hi = __float2bfloat16_rn(w);
    float res = w - __bfloat162float(hi);
    __nv_bfloat16 lo = __float2bfloat16_rn(res);
    g_wbh[(l * 128 + n) * 128 + k] = hi;   // B[n][k] = W[k][n]
    g_wbl[(l * 128 + n) * 128 + k] = lo;
}

// ---------------- bf16x3 tensor-core GEMM + fused scores ----------------
__global__ __launch_bounds__(256, 1) void k_gemm(int layer,
                                                 const float* __restrict__ asrc,
                                                 const float* __restrict__ adst) {
    extern __shared__ char smem[];
    uint32_t sb = smem_u32(smem);
    const int tid  = threadIdx.x;
    const int wid  = tid >> 5;
    const int lane = tid & 31;
    const int wm   = wid & 3;
    const int wn   = wid >> 2;
    const int g    = lane >> 2;
    const int t    = lane & 3;
    const int rowbase = blockIdx.x * 128;

    const float4* Ag4 = (const float4*)g_h;
#pragma unroll
    for (int j = 0; j < 16; j++) {
        int idx = tid + j * 256;
        int r = idx >> 5, c4 = idx & 31;
        int gr = rowbase + r;
        float4 v = (gr < N_NODES) ? Ag4[gr * 32 + c4] : make_float4(0.f, 0.f, 0.f, 0.f);
        __nv_bfloat16 h0 = __float2bfloat16_rn(v.x);
        __nv_bfloat16 h1 = __float2bfloat16_rn(v.y);
        __nv_bfloat16 h2 = __float2bfloat16_rn(v.z);
        __nv_bfloat16 h3 = __float2bfloat16_rn(v.w);
        __nv_bfloat16 l0 = __float2bfloat16_rn(v.x - __bfloat162float(h0));
        __nv_bfloat16 l1 = __float2bfloat16_rn(v.y - __bfloat162float(h1));
        __nv_bfloat16 l2 = __float2bfloat16_rn(v.z - __bfloat162float(h2));
        __nv_bfloat16 l3 = __float2bfloat16_rn(v.w - __bfloat162float(h3));
        uint32_t off = (uint32_t)(r * 272 + c4 * 8);
        *(uint2*)(smem + SM_AH + off) = make_uint2(bf2_bits(h0, h1), bf2_bits(h2, h3));
        *(uint2*)(smem + SM_AL + off) = make_uint2(bf2_bits(l0, l1), bf2_bits(l2, l3));
    }
    const uint4* wh4 = (const uint4*)(g_wbh + layer * 16384);
    const uint4* wl4 = (const uint4*)(g_wbl + layer * 16384);
#pragma unroll
    for (int j = 0; j < 8; j++) {
        int idx = tid + j * 256;
        int r = idx >> 4, c8 = idx & 15;
        uint32_t off = (uint32_t)(r * 272 + c8 * 16);
        *(uint4*)(smem + SM_BH + off) = wh4[r * 16 + c8];
        *(uint4*)(smem + SM_BL + off) = wl4[r * 16 + c8];
    }
    __syncthreads();

    const int q  = lane >> 3;
    const int rr = lane & 7;
    uint32_t aOff = (uint32_t)((wm * 32 + ((q & 1) << 3) + rr) * 272 + ((q >> 1) << 4));
    uint32_t bOff = (uint32_t)((wn * 64 + ((q >> 1) << 3) + rr) * 272 + ((q & 1) << 4));
    uint32_t aH = sb + SM_AH + aOff, aL = sb + SM_AL + aOff;
    uint32_t bH = sb + SM_BH + bOff, bL = sb + SM_BL + bOff;

    float acc[2][8][4];
#pragma unroll
    for (int i = 0; i < 2; i++)
#pragma unroll
        for (int jn = 0; jn < 8; jn++)
#pragma unroll
            for (int c = 0; c < 4; c++) acc[i][jn][c] = 0.f;

#pragma unroll
    for (int ks = 0; ks < 8; ks++) {
        const uint32_t kb = ks * 32;
        uint32_t ah[2][4], al[2][4], b[4][4];
#pragma unroll
        for (int i = 0; i < 2; i++) {
            ldsm_x4(ah[i][0], ah[i][1], ah[i][2], ah[i][3], aH + kb + i * 4352);
            ldsm_x4(al[i][0], al[i][1], al[i][2], al[i][3], aL + kb + i * 4352);
        }
#pragma unroll
        for (int p = 0; p < 4; p++)
            ldsm_x4(b[p][0], b[p][1], b[p][2], b[p][3], bH + kb + p * 4352);
#pragma unroll
        for (int i = 0; i < 2; i++)
#pragma unroll
            for (int p = 0; p < 4; p++) {
                mma_bf16(acc[i][2 * p],     ah[i], b[p][0], b[p][1]);
                mma_bf16(acc[i][2 * p + 1], ah[i], b[p][2], b[p][3]);
            }
#pragma unroll
        for (int i = 0; i < 2; i++)
#pragma unroll
            for (int p = 0; p < 4; p++) {
                mma_bf16(acc[i][2 * p],     al[i], b[p][0], b[p][1]);
                mma_bf16(acc[i][2 * p + 1], al[i], b[p][2], b[p][3]);
            }
#pragma unroll
        for (int p = 0; p < 4; p++)
            ldsm_x4(b[p][0], b[p][1], b[p][2], b[p][3], bL + kb + p * 4352);
#pragma unroll
        for (int i = 0; i < 2; i++)
#pragma unroll
            for (int p = 0; p < 4; p++) {
                mma_bf16(acc[i][2 * p],     ah[i], b[p][0], b[p][1]);
                mma_bf16(acc[i][2 * p + 1], ah[i], b[p][2], b[p][3]);
            }
    }

    float sAr[2][2] = {{0.f, 0.f}, {0.f, 0.f}};
    float sBr[2][2] = {{0.f, 0.f}, {0.f, 0.f}};
#pragma unroll
    for (int jn = 0; jn < 8; jn++) {
        int col = wn * 64 + jn * 8 + 2 * t;
        float as0 = asrc[col], as1 = asrc[col + 1];
        float ad0 = adst[col], ad1 = adst[col + 1];
#pragma unroll
        for (int i = 0; i < 2; i++) {
            float* c = acc[i][jn];
            sAr[i][0] += c[0] * as0 + c[1] * as1;
            sAr[i][1] += c[2] * as0 + c[3] * as1;
            sBr[i][0] += c[0] * ad0 + c[1] * ad1;
            sBr[i][1] += c[2] * ad0 + c[3] * ad1;
            int row = rowbase + wm * 32 + i * 16 + g;
            if (row < N_NODES)
                *(__half2*)&g_hw[row * 128 + col] = __floats2half2_rn(c[0], c[1]);
            if (row + 8 < N_NODES)
                *(__half2*)&g_hw[(row + 8) * 128 + col] = __floats2half2_rn(c[2], c[3]);
        }
    }
#pragma unroll
    for (int off = 1; off <= 2; off <<= 1) {
#pragma unroll
        for (int i = 0; i < 2; i++)
#pragma unroll
            for (int h = 0; h < 2; h++) {
                sAr[i][h] += __shfl_xor_sync(0xffffffffu, sAr[i][h], off);
                sBr[i][h] += __shfl_xor_sync(0xffffffffu, sBr[i][h], off);
            }
    }
    float* sA2 = (float*)(smem + SM_SA);
    float* sB2 = (float*)(smem + SM_SB);
    if (t == 0) {
#pragma unroll
        for (int i = 0; i < 2; i++)
#pragma unroll
            for (int h = 0; h < 2; h++) {
                int rl = wm * 32 + i * 16 + h * 8 + g;
                sA2[wn * 128 + rl] = sAr[i][h];
                sB2[wn * 128 + rl] = sBr[i][h];
            }
    }
    __syncthreads();
    if (tid < 128) {
        int gr = rowbase + tid;
        if (gr < N_NODES) {
            g_ssrc[gr] = sA2[tid] + sA2[128 + tid];
            g_sdst[gr] = sB2[tid] + sB2[128 + tid];
        }
    }
}

// ---------------- single-pass online-softmax aggregation (fp16 gather) ----------------
__global__ void k_agg(const float* __restrict__ bias, int relu) {
    int node = (blockIdx.x * blockDim.x + threadIdx.x) >> 5;
    int lane = threadIdx.x & 31;
    if (node >= N_NODES) return;

    const int beg = g_off[node];
    const int end = g_off[node + 1];
    const float sd = g_sdst[node];

    float m = -1e30f;
    float denl = 0.f;
    float4 acc = make_float4(0.f, 0.f, 0.f, 0.f);

    for (int base = beg; base < end; base += 32) {
        int e = base + lane;
        bool valid = (e < end);
        int srcr = valid ? g_csrc[e] : 0;
        float tt = -1e30f;
        if (valid) {
            float s = g_ssrc[srcr] + sd;
            tt = (s > 0.f) ? s : NEG_SLOPE * s;
        }
        float mc = tt;
#pragma unroll
        for (int off = 16; off > 0; off >>= 1)
            mc = fmaxf(mc, __shfl_xor_sync(0xffffffffu, mc, off));
        if (mc > m) {
            float f = __expf(m - mc);
            denl *= f;
            acc.x *= f; acc.y *= f; acc.z *= f; acc.w *= f;
            m = mc;
        }
        float w = valid ? __expf(tt - m) : 0.f;
        denl += w;
        int n = end - base; if (n > 32) n = 32;
        for (int j = 0; j < n; j++) {
            float wj = __shfl_sync(0xffffffffu, w, j);
            int   sj = __shfl_sync(0xffffffffu, srcr, j);
            uint2 raw = *(const uint2*)(g_hw + sj * 128 + lane * 4);
            float2 f0 = __half22float2(*(__half2*)&raw.x);
            float2 f1 = __half22float2(*(__half2*)&raw.y);
            acc.x += wj * f0.x; acc.y += wj * f0.y;
            acc.z += wj * f1.x; acc.w += wj * f1.y;
        }
    }
    float den = denl;
#pragma unroll
    for (int off = 16; off > 0; off >>= 1)
        den += __shfl_xor_sync(0xffffffffu, den, off);

    float inv = 1.f / den;
    float4 b = ((const float4*)bias)[lane];
    float4 o;
    o.x = acc.x * inv + b.x; o.y = acc.y * inv + b.y;
    o.z = acc.z * inv + b.z; o.w = acc.w * inv + b.w;
    if (relu) {
        o.x = fmaxf(o.x, 0.f); o.y = fmaxf(o.y, 0.f);
        o.z = fmaxf(o.z, 0.f); o.w = fmaxf(o.w, 0.f);
    }
    ((float4*)g_h)[node * 32 + lane] = o;
}

// ---------------- fused pooling + projection ----------------
__global__ void k_poolfinal(const float* __restrict__ Wout,
                            const float* __restrict__ bout,
                            float* __restrict__ out) {
    __shared__ float pooled[HID];
    int g = blockIdx.x;       // 64 graphs
    int c = threadIdx.x;      // 128 channels
    int s = g_gstart[g], e = g_gstart[g + 1];
    float a0 = 0.f, a1 = 0.f, a2 = 0.f, a3 = 0.f;
    int i = s;
    for (; i + 3 < e; i += 4) {
        a0 += g_h[(i + 0) * HID + c];
        a1 += g_h[(i + 1) * HID + c];
        a2 += g_h[(i + 2) * HID + c];
        a3 += g_h[(i + 3) * HID + c];
    }
    for (; i < e; i++) a0 += g_h[i * HID + c];
    float cnt = (float)(e - s);
    pooled[c] = (a0 + a1 + a2 + a3) / fmaxf(cnt, 1.f);
    __syncthreads();
    if (c < OUT_CH) {
        float acc = 0.f;
#pragma unroll 4
        for (int k = 0; k < HID; k++)
            acc += pooled[k] * Wout[k * OUT_CH + c];
        out[g * OUT_CH + c] = acc + bout[c];
    }
}

// ---------------- launch ----------------
extern "C" void kernel_launch(void* const* d_in, const int* in_sizes, int n_in,
                              void* d_out, int out_size) {
    const int*   x     = (const int*)  d_in[0];
    const int*   ei    = (const int*)  d_in[1];
    const int*   batch = (const int*)  d_in[2];
    const float* emb   = (const float*)d_in[3];
    const float* Ws    = (const float*)d_in[4];
    const float* asrc  = (const float*)d_in[5];
    const float* adst  = (const float*)d_in[6];
    const float* bs    = (const float*)d_in[7];
    const float* Wout  = (const float*)d_in[8];
    const float* bout  = (const float*)d_in[9];
    float* out = (float*)d_out;

    const int* src = ei;
    const int* dst = ei + N_EDGES;

    static cudaStream_t s1 = 0;
    static cudaEvent_t evFork = 0, evJoin = 0;
    static int inited = 0;
    if (!inited) {
        cudaStreamCreateWithFlags(&s1, cudaStreamNonBlocking);
        cudaEventCreateWithFlags(&evFork, cudaEventDisableTiming);
        cudaEventCreateWithFlags(&evJoin, cudaEventDisableTiming);
        cudaFuncSetAttribute(k_gemm, cudaFuncAttributeMaxDynamicSharedMemorySize, GEMM_SMEM);
        inited = 1;
    }

    cudaEventRecord(evFork, 0);
    cudaStreamWaitEvent(s1, evFork, 0);

    // side stream: CSR build + graph bounds
    k_zero<<<(N_NODES + 255) / 256, 256, 0, s1>>>();
    k_hist<<<1024, 256, 0, s1>>>(dst);
    k_scan1<<<SCAN_BLOCKS, 1024, 0, s1>>>();
    k_scan23<<<(N_NODES + 255) / 256, 256, 0, s1>>>(batch);
    k_fillcsr<<<1024, 256, 0, s1>>>(src, dst);

    // main stream: W prep + embedding + layer-0 GEMM
    const int gemm_blocks = (N_NODES + 127) / 128;
    const int warp_blocks = (N_NODES * 32 + 255) / 256;
    k_prepw<<<(3 * 16384 + 255) / 256, 256>>>(Ws);
    k_embed<<<(N_NODES * 32 + 255) / 256, 256>>>(x, emb);
    k_gemm<<<gemm_blocks, 256, GEMM_SMEM>>>(0, asrc, adst);

    cudaEventRecord(evJoin, s1);
    cudaStreamWaitEvent(0, evJoin, 0);

    k_agg<<<warp_blocks, 256>>>(bs, 1);
    for (int l = 1; l < 3; l++) {
        k_gemm<<<gemm_blocks, 256, GEMM_SMEM>>>(l, asrc + l * HID, adst + l * HID);
        k_agg<<<warp_blocks, 256>>>(bs + l * HID, (l < 2) ? 1 : 0);
    }

    k_poolfinal<<<N_GRAPHS, HID>>>(Wout, bout, out);
}